// round 1
// baseline (speedup 1.0000x reference)
#include <cuda_runtime.h>
#include <cuda_bf16.h>
#include <cstdint>

#define N_ROWS 8192
#define D_DIM  512
#define BM 128
#define BN 128
#define BK 32
#define LDS_STRIDE 40   // halves; 80B row stride, 16B-aligned, conflict-free for ldmatrix
#define JCHUNK 2048     // columns per CTA (16 j-tiles)

// exp(10) exactly (diagonal term: sim_ii == 1 in fp32)
#define EXP10 22026.465794806718f
#define LOG2E_OVER_T 14.426950408889634f   // (1/0.1) * log2(e)

// ---- scratch (no allocation allowed) ----
__device__ __nv_bfloat16 g_fn[N_ROWS * D_DIM];
__device__ float g_pos[N_ROWS];
__device__ float g_tot[N_ROWS];
__device__ int   g_cl[N_ROWS];

// ---------------------------------------------------------------------------
// init: zero accumulators, convert cluster ids (handles int32 or int64 input)
// ---------------------------------------------------------------------------
__global__ void init_kernel(const int* ca) {
    int i = blockIdx.x * blockDim.x + threadIdx.x;
    if (i >= N_ROWS) return;
    // int64 detection: little-endian high words are all zero (values 0..63).
    bool is64 = (ca[1] == 0) && (ca[3] == 0) && (ca[5] == 0) && (ca[7] == 0);
    g_cl[i]  = is64 ? ca[2 * i] : ca[i];
    g_pos[i] = 0.0f;
    g_tot[i] = 0.0f;
}

// ---------------------------------------------------------------------------
// normalize: one block per row, fp32 norm, write bf16
// ---------------------------------------------------------------------------
__global__ void norm_kernel(const float* __restrict__ f) {
    int row = blockIdx.x;
    const float* fr = f + (size_t)row * D_DIM;
    float v[4];
    float ss = 0.0f;
#pragma unroll
    for (int k = 0; k < 4; k++) {
        v[k] = fr[threadIdx.x + 128 * k];
        ss += v[k] * v[k];
    }
#pragma unroll
    for (int o = 16; o; o >>= 1) ss += __shfl_xor_sync(0xFFFFFFFFu, ss, o);
    __shared__ float s[4];
    if ((threadIdx.x & 31) == 0) s[threadIdx.x >> 5] = ss;
    __syncthreads();
    ss = s[0] + s[1] + s[2] + s[3];
    float norm = sqrtf(ss);
    float r = 1.0f / fmaxf(norm, 1e-12f);
#pragma unroll
    for (int k = 0; k < 4; k++)
        g_fn[(size_t)row * D_DIM + threadIdx.x + 128 * k] = __float2bfloat16(v[k] * r);
}

// ---------------------------------------------------------------------------
// mma helpers
// ---------------------------------------------------------------------------
__device__ __forceinline__ uint32_t smem_u32(const void* p) {
    return (uint32_t)__cvta_generic_to_shared(p);
}
__device__ __forceinline__ void ldsm_x4(uint32_t addr, uint32_t& r0, uint32_t& r1,
                                        uint32_t& r2, uint32_t& r3) {
    asm volatile("ldmatrix.sync.aligned.m8n8.x4.shared.b16 {%0,%1,%2,%3},[%4];"
                 : "=r"(r0), "=r"(r1), "=r"(r2), "=r"(r3) : "r"(addr));
}
__device__ __forceinline__ void mma16816(float* c, uint32_t a0, uint32_t a1,
                                         uint32_t a2, uint32_t a3,
                                         uint32_t b0, uint32_t b1) {
    asm volatile(
        "mma.sync.aligned.m16n8k16.row.col.f32.bf16.bf16.f32 "
        "{%0,%1,%2,%3},{%4,%5,%6,%7},{%8,%9},{%0,%1,%2,%3};"
        : "+f"(c[0]), "+f"(c[1]), "+f"(c[2]), "+f"(c[3])
        : "r"(a0), "r"(a1), "r"(a2), "r"(a3), "r"(b0), "r"(b1));
}

// ---------------------------------------------------------------------------
// fused GEMM + exp + masked row-sum
// grid: (N/JCHUNK, N/BM) = (4, 64), 256 threads (8 warps: 4 M x 2 N)
// warp tile 32(M) x 64(N)
// ---------------------------------------------------------------------------
__global__ void __launch_bounds__(256, 2) gemm_kernel() {
    __shared__ __nv_bfloat16 As[BM * LDS_STRIDE];
    __shared__ __nv_bfloat16 Bs[BN * LDS_STRIDE];
    __shared__ int s_cj[BN];

    const int tid  = threadIdx.x;
    const int lane = tid & 31;
    const int w    = tid >> 5;
    const int wm   = w & 3;       // 0..3 -> M offset
    const int wn   = w >> 2;      // 0..1 -> N offset
    const int i0   = blockIdx.y * BM;
    const int jc0  = blockIdx.x * JCHUNK;

    // rows this thread owns (accumulator layout of m16n8k16)
    const int rbase = wm * 32 + (lane >> 2);
    int ci[4];
#pragma unroll
    for (int r = 0; r < 4; r++) ci[r] = g_cl[i0 + rbase + r * 8];

    float pos[4] = {0, 0, 0, 0};
    float tot[4] = {0, 0, 0, 0};

    // gmem staging indices: 256 threads cover 64 rows x 32 halves per pass
    const int grow0 = tid >> 2;          // 0..63
    const int gcol  = (tid & 3) * 8;     // halves
    const __nv_bfloat16* __restrict__ gA = g_fn + (size_t)i0 * D_DIM;

    // smem store addresses
    __nv_bfloat16* sA0 = &As[(grow0)      * LDS_STRIDE + gcol];
    __nv_bfloat16* sA1 = &As[(grow0 + 64) * LDS_STRIDE + gcol];
    __nv_bfloat16* sB0 = &Bs[(grow0)      * LDS_STRIDE + gcol];
    __nv_bfloat16* sB1 = &Bs[(grow0 + 64) * LDS_STRIDE + gcol];

    // ldmatrix addresses
    const int a_row = wm * 32 + (lane & 15);
    const int a_col = (lane >> 4) << 3;
    uint32_t a_addr_base = smem_u32(&As[a_row * LDS_STRIDE + a_col]);
    const int b_row = wn * 64 + (lane & 7) + ((lane >> 4) << 3);
    const int b_col = ((lane >> 3) & 1) << 3;
    uint32_t b_addr_base = smem_u32(&Bs[b_row * LDS_STRIDE + b_col]);

    for (int jt = 0; jt < JCHUNK / BN; jt++) {
        const int j = jc0 + jt * BN;
        const __nv_bfloat16* __restrict__ gB = g_fn + (size_t)j * D_DIM;

        __syncthreads();                       // prior epilogue / ldsm done
        if (tid < BN) s_cj[tid] = g_cl[j + tid];

        float acc[2][8][4];
#pragma unroll
        for (int mi = 0; mi < 2; mi++)
#pragma unroll
            for (int ni = 0; ni < 8; ni++)
#pragma unroll
                for (int v = 0; v < 4; v++) acc[mi][ni][v] = 0.0f;

        for (int kk = 0; kk < D_DIM; kk += BK) {
            uint4 ra0 = *(const uint4*)(gA + (size_t)(grow0)      * D_DIM + kk + gcol);
            uint4 ra1 = *(const uint4*)(gA + (size_t)(grow0 + 64) * D_DIM + kk + gcol);
            uint4 rb0 = *(const uint4*)(gB + (size_t)(grow0)      * D_DIM + kk + gcol);
            uint4 rb1 = *(const uint4*)(gB + (size_t)(grow0 + 64) * D_DIM + kk + gcol);
            __syncthreads();
            *(uint4*)sA0 = ra0;
            *(uint4*)sA1 = ra1;
            *(uint4*)sB0 = rb0;
            *(uint4*)sB1 = rb1;
            __syncthreads();

#pragma unroll
            for (int s = 0; s < 2; s++) {
                uint32_t a[2][4];
#pragma unroll
                for (int mi = 0; mi < 2; mi++)
                    ldsm_x4(a_addr_base + (uint32_t)((mi * 16 * LDS_STRIDE + s * 16) * 2),
                            a[mi][0], a[mi][1], a[mi][2], a[mi][3]);
#pragma unroll
                for (int np = 0; np < 4; np++) {    // pairs of n-frags
                    uint32_t b0, b1, b2, b3;
                    ldsm_x4(b_addr_base + (uint32_t)((np * 16 * LDS_STRIDE + s * 16) * 2),
                            b0, b1, b2, b3);
#pragma unroll
                    for (int mi = 0; mi < 2; mi++) {
                        mma16816(acc[mi][np * 2],     a[mi][0], a[mi][1], a[mi][2], a[mi][3], b0, b1);
                        mma16816(acc[mi][np * 2 + 1], a[mi][0], a[mi][1], a[mi][2], a[mi][3], b2, b3);
                    }
                }
            }
        }

        // fused epilogue: exp + mask + accumulate into per-row register sums
#pragma unroll
        for (int ni = 0; ni < 8; ni++) {
            const int col0 = wn * 64 + ni * 8 + (lane & 3) * 2;
            const int2 cjp = *(const int2*)&s_cj[col0];
            const int gj0 = j + col0;
#pragma unroll
            for (int mi = 0; mi < 2; mi++) {
#pragma unroll
                for (int v = 0; v < 4; v++) {
                    const int ridx = mi * 2 + (v >> 1);
                    const int grow = i0 + rbase + ridx * 8;
                    const int gcolv = gj0 + (v & 1);
                    float e;
                    if (grow == gcolv) {
                        e = EXP10;    // exact diagonal: sim_ii == 1
                    } else {
                        e = exp2f(acc[mi][ni][v] * LOG2E_OVER_T);
                    }
                    const int cjv = (v & 1) ? cjp.y : cjp.x;
                    tot[ridx] += e;
                    if (ci[ridx] == cjv) pos[ridx] += e;
                }
            }
        }
    }

    // reduce across the 4 lanes sharing each row, then global atomics
#pragma unroll
    for (int r = 0; r < 4; r++) {
#pragma unroll
        for (int o = 1; o <= 2; o <<= 1) {
            pos[r] += __shfl_xor_sync(0xFFFFFFFFu, pos[r], o);
            tot[r] += __shfl_xor_sync(0xFFFFFFFFu, tot[r], o);
        }
    }
    if ((lane & 3) == 0) {
#pragma unroll
        for (int r = 0; r < 4; r++) {
            atomicAdd(&g_pos[i0 + rbase + r * 8], pos[r]);
            atomicAdd(&g_tot[i0 + rbase + r * 8], tot[r]);
        }
    }
}

// ---------------------------------------------------------------------------
// final loss reduction
// ---------------------------------------------------------------------------
__global__ void loss_kernel(float* __restrict__ out) {
    __shared__ float s[8];
    float sum = 0.0f;
    for (int i = threadIdx.x; i < N_ROWS; i += blockDim.x) {
        float p = g_pos[i];
        float t = g_tot[i];
        sum += logf((t + 1e-8f) / p);   // == -log(pos/(pos+neg+eps))
    }
#pragma unroll
    for (int o = 16; o; o >>= 1) sum += __shfl_xor_sync(0xFFFFFFFFu, sum, o);
    if ((threadIdx.x & 31) == 0) s[threadIdx.x >> 5] = sum;
    __syncthreads();
    if (threadIdx.x < 32) {
        float v = (threadIdx.x < 8) ? s[threadIdx.x] : 0.0f;
#pragma unroll
        for (int o = 4; o; o >>= 1) v += __shfl_xor_sync(0xFFFFFFFFu, v, o);
        if (threadIdx.x == 0) out[0] = v;
    }
}

// ---------------------------------------------------------------------------
extern "C" void kernel_launch(void* const* d_in, const int* in_sizes, int n_in,
                              void* d_out, int out_size) {
    const float* feat = (const float*)d_in[0];
    const int*   ca   = (const int*)d_in[1];   // int32 or int64 (auto-detected)

    init_kernel<<<(N_ROWS + 255) / 256, 256>>>(ca);
    norm_kernel<<<N_ROWS, 128>>>(feat);
    dim3 grid(N_ROWS / JCHUNK, N_ROWS / BM);   // (4, 64)
    gemm_kernel<<<grid, 256>>>();
    loss_kernel<<<1, 256>>>((float*)d_out);
}

// round 3
// speedup vs baseline: 1.0078x; 1.0078x over previous
#include <cuda_runtime.h>
#include <cuda_bf16.h>
#include <cstdint>

#define N_ROWS 8192
#define D_DIM  512
#define BM 128
#define BN 128
#define BK 32
#define LDS_STRIDE 40        // halves; 80B row pitch, conflict-free for ldmatrix
#define JCHUNK 2048
#define NJT (JCHUNK / BN)    // 16 j-tiles per CTA
#define NKS (D_DIM / BK)     // 16 k-steps per j-tile
#define TOTAL_STEPS (NJT * NKS)   // 256
#define STAGES 3
#define STAGE_HALVES (2 * BM * LDS_STRIDE)   // A + B tile per stage = 10240 halves
#define SMEM_BYTES (STAGES * STAGE_HALVES * 2)  // 61440 B

#define EXP10 22026.465794806718f
#define SCALE 14.426950408889634f   // (1/0.1)*log2(e), folded into g_fb

// ---- scratch ----
__device__ __nv_bfloat16 g_fa[N_ROWS * D_DIM];   // normalized
__device__ __nv_bfloat16 g_fb[N_ROWS * D_DIM];   // normalized * SCALE
__device__ float g_pos[N_ROWS];
__device__ float g_tot[N_ROWS];
__device__ int   g_cl[N_ROWS];

// =============================== helpers ===================================
__device__ __forceinline__ uint32_t smem_u32(const void* p) {
    return (uint32_t)__cvta_generic_to_shared(p);
}
__device__ __forceinline__ void cp16(uint32_t saddr, const void* g) {
    asm volatile("cp.async.cg.shared.global [%0], [%1], 16;" :: "r"(saddr), "l"(g));
}
__device__ __forceinline__ void ldsm_x4(uint32_t addr, uint32_t& r0, uint32_t& r1,
                                        uint32_t& r2, uint32_t& r3) {
    asm volatile("ldmatrix.sync.aligned.m8n8.x4.shared.b16 {%0,%1,%2,%3},[%4];"
                 : "=r"(r0), "=r"(r1), "=r"(r2), "=r"(r3) : "r"(addr));
}
__device__ __forceinline__ void mma16816(float* c, uint32_t a0, uint32_t a1,
                                         uint32_t a2, uint32_t a3,
                                         uint32_t b0, uint32_t b1) {
    asm volatile(
        "mma.sync.aligned.m16n8k16.row.col.f32.bf16.bf16.f32 "
        "{%0,%1,%2,%3},{%4,%5,%6,%7},{%8,%9},{%0,%1,%2,%3};"
        : "+f"(c[0]), "+f"(c[1]), "+f"(c[2]), "+f"(c[3])
        : "r"(a0), "r"(a1), "r"(a2), "r"(a3), "r"(b0), "r"(b1));
}

// =============================== small kernels ==============================
__global__ void init_kernel(const int* ca, float* out) {
    int i = blockIdx.x * blockDim.x + threadIdx.x;
    if (i == 0) out[0] = 0.0f;
    if (i >= N_ROWS) return;
    bool is64 = (ca[1] == 0) && (ca[3] == 0) && (ca[5] == 0) && (ca[7] == 0);
    g_cl[i]  = is64 ? ca[2 * i] : ca[i];
    g_pos[i] = 0.0f;
    g_tot[i] = 0.0f;
}

__global__ void norm_kernel(const float* __restrict__ f) {
    int row = blockIdx.x;
    const float* fr = f + (size_t)row * D_DIM;
    float v[4];
    float ss = 0.0f;
#pragma unroll
    for (int k = 0; k < 4; k++) { v[k] = fr[threadIdx.x + 128 * k]; ss += v[k] * v[k]; }
#pragma unroll
    for (int o = 16; o; o >>= 1) ss += __shfl_xor_sync(0xFFFFFFFFu, ss, o);
    __shared__ float s[4];
    if ((threadIdx.x & 31) == 0) s[threadIdx.x >> 5] = ss;
    __syncthreads();
    ss = s[0] + s[1] + s[2] + s[3];
    float r = 1.0f / fmaxf(sqrtf(ss), 1e-12f);
#pragma unroll
    for (int k = 0; k < 4; k++) {
        float x = v[k] * r;
        size_t idx = (size_t)row * D_DIM + threadIdx.x + 128 * k;
        g_fa[idx] = __float2bfloat16(x);
        g_fb[idx] = __float2bfloat16(x * SCALE);
    }
}

__global__ void loss_kernel(float* __restrict__ out) {
    int i = blockIdx.x * blockDim.x + threadIdx.x;
    float sum = logf((g_tot[i] + 1e-8f) / g_pos[i]);
#pragma unroll
    for (int o = 16; o; o >>= 1) sum += __shfl_xor_sync(0xFFFFFFFFu, sum, o);
    __shared__ float s[8];
    if ((threadIdx.x & 31) == 0) s[threadIdx.x >> 5] = sum;
    __syncthreads();
    if (threadIdx.x < 32) {
        float v = (threadIdx.x < 8) ? s[threadIdx.x] : 0.0f;
#pragma unroll
        for (int o = 4; o; o >>= 1) v += __shfl_xor_sync(0xFFFFFFFFu, v, o);
        if (threadIdx.x == 0) atomicAdd(out, v);
    }
}

// =============================== main GEMM ==================================
// grid (4, 64), 256 threads = 8 warps (4 M x 2 N), warp tile 32x64
// 3-stage cp.async pipeline over g = jt*16 + kstep (256 steps, continuous)
__global__ void __launch_bounds__(256, 2) gemm_hmma() {
    extern __shared__ __nv_bfloat16 sm[];

    const int tid  = threadIdx.x;
    const int lane = tid & 31;
    const int w    = tid >> 5;
    const int wm   = w & 3;
    const int wn   = w >> 2;
    const int i0   = blockIdx.y * BM;
    const int jc0  = blockIdx.x * JCHUNK;

    // ---- cp.async staging geometry: thread -> (row, 16B segment) ----
    const int grow0 = tid >> 2;                 // 0..63
    const int gcol  = (tid & 3) * 8;            // halves
    const uint32_t s_off0 = (uint32_t)((grow0 * LDS_STRIDE + gcol) * 2);
    const uint32_t s_off1 = (uint32_t)(((grow0 + 64) * LDS_STRIDE + gcol) * 2);
    const __nv_bfloat16* gA0 = g_fa + (size_t)(i0 + grow0) * D_DIM + gcol;
    const __nv_bfloat16* gB0 = g_fb + (size_t)(jc0 + grow0) * D_DIM + gcol;
    const uint32_t sm_base = smem_u32(sm);

    // ---- ldmatrix geometry ----
    const int a_row = wm * 32 + (lane & 15);
    const int a_col = (lane >> 4) << 3;
    const uint32_t a_off = (uint32_t)((a_row * LDS_STRIDE + a_col) * 2);
    const int b_row = wn * 64 + (lane & 7) + ((lane >> 4) << 3);
    const int b_col = ((lane >> 3) & 1) << 3;
    const uint32_t b_off = (uint32_t)((b_row * LDS_STRIDE + b_col) * 2) +
                           (uint32_t)(BM * LDS_STRIDE * 2);   // B after A in stage

    // ---- per-thread output rows ----
    const int rbase = wm * 32 + (lane >> 2);
    int ci[4];
#pragma unroll
    for (int r = 0; r < 4; r++) ci[r] = g_cl[i0 + rbase + r * 8];
    float pos[4] = {0, 0, 0, 0};
    float tot[4] = {0, 0, 0, 0};

    float acc[2][8][4];
#pragma unroll
    for (int mi = 0; mi < 2; mi++)
#pragma unroll
        for (int ni = 0; ni < 8; ni++)
#pragma unroll
            for (int v = 0; v < 4; v++) acc[mi][ni][v] = 0.0f;

    // ---- prefetch lambda ----
    auto prefetch = [&](int g) {
        const int jt = g >> 4;
        const int kk = (g & 15) << 5;
        const uint32_t st = (uint32_t)(g % STAGES) * (STAGE_HALVES * 2);
        const __nv_bfloat16* a = gA0 + kk;
        cp16(sm_base + st + s_off0, a);
        cp16(sm_base + st + s_off1, a + 64 * D_DIM);
        const __nv_bfloat16* b = gB0 + (size_t)jt * BN * D_DIM + kk;
        const uint32_t bs = st + (uint32_t)(BM * LDS_STRIDE * 2);
        cp16(sm_base + bs + s_off0, b);
        cp16(sm_base + bs + s_off1, b + 64 * D_DIM);
        asm volatile("cp.async.commit_group;" ::: "memory");
    };

    prefetch(0);
    prefetch(1);

    for (int g = 0; g < TOTAL_STEPS; g++) {
        asm volatile("cp.async.wait_group 1;" ::: "memory");
        __syncthreads();
        if (g + 2 < TOTAL_STEPS) prefetch(g + 2);

        const uint32_t stb = sm_base + (uint32_t)(g % STAGES) * (STAGE_HALVES * 2);
        const uint32_t sa = stb + a_off;
        const uint32_t sbb = stb + b_off;

#pragma unroll
        for (int s = 0; s < 2; s++) {
            uint32_t a[2][4];
#pragma unroll
            for (int mi = 0; mi < 2; mi++)
                ldsm_x4(sa + (uint32_t)((mi * 16 * LDS_STRIDE + s * 16) * 2),
                        a[mi][0], a[mi][1], a[mi][2], a[mi][3]);
#pragma unroll
            for (int np = 0; np < 4; np++) {
                uint32_t b0, b1, b2, b3;
                ldsm_x4(sbb + (uint32_t)((np * 16 * LDS_STRIDE + s * 16) * 2),
                        b0, b1, b2, b3);
#pragma unroll
                for (int mi = 0; mi < 2; mi++) {
                    mma16816(acc[mi][np * 2],     a[mi][0], a[mi][1], a[mi][2], a[mi][3], b0, b1);
                    mma16816(acc[mi][np * 2 + 1], a[mi][0], a[mi][1], a[mi][2], a[mi][3], b2, b3);
                }
            }
        }

        // ---- epilogue at j-tile boundary (registers only; scale folded in B) ----
        if ((g & 15) == 15) {
            const int jt = g >> 4;
            const int j0 = jc0 + jt * BN;
            const bool diag = (j0 == i0);
#pragma unroll
            for (int ni = 0; ni < 8; ni++) {
                const int colb = wn * 64 + ni * 8 + (lane & 3) * 2;
                const int2 cjp = *(const int2*)&g_cl[j0 + colb];
#pragma unroll
                for (int mi = 0; mi < 2; mi++) {
#pragma unroll
                    for (int v = 0; v < 4; v++) {
                        const int ridx = mi * 2 + (v >> 1);
                        float e = exp2f(acc[mi][ni][v]);
                        if (diag && (rbase + ridx * 8 == colb + (v & 1))) e = EXP10;
                        tot[ridx] += e;
                        if (ci[ridx] == ((v & 1) ? cjp.y : cjp.x)) pos[ridx] += e;
                        acc[mi][ni][v] = 0.0f;
                    }
                }
            }
        }
    }

    // reduce across the 4 lanes sharing each row, then global atomics
#pragma unroll
    for (int r = 0; r < 4; r++) {
#pragma unroll
        for (int o = 1; o <= 2; o <<= 1) {
            pos[r] += __shfl_xor_sync(0xFFFFFFFFu, pos[r], o);
            tot[r] += __shfl_xor_sync(0xFFFFFFFFu, tot[r], o);
        }
    }
    if ((lane & 3) == 0) {
#pragma unroll
        for (int r = 0; r < 4; r++) {
            atomicAdd(&g_pos[i0 + rbase + r * 8], pos[r]);
            atomicAdd(&g_tot[i0 + rbase + r * 8], tot[r]);
        }
    }
}

// =============================== launch =====================================
extern "C" void kernel_launch(void* const* d_in, const int* in_sizes, int n_in,
                              void* d_out, int out_size) {
    const float* feat = (const float*)d_in[0];
    const int*   ca   = (const int*)d_in[1];

    static bool attr_done = false;
    if (!attr_done) {
        cudaFuncSetAttribute(gemm_hmma, cudaFuncAttributeMaxDynamicSharedMemorySize,
                             SMEM_BYTES);
        attr_done = true;
    }

    init_kernel<<<(N_ROWS + 255) / 256, 256>>>(ca, (float*)d_out);
    norm_kernel<<<N_ROWS, 128>>>(feat);
    dim3 grid(N_ROWS / JCHUNK, N_ROWS / BM);   // (4, 64)
    gemm_hmma<<<grid, 256, SMEM_BYTES>>>();
    loss_kernel<<<N_ROWS / 256, 256>>>((float*)d_out);
}

// round 4
// speedup vs baseline: 1.6913x; 1.6783x over previous
#include <cuda_runtime.h>
#include <cuda_bf16.h>
#include <cstdint>

#define N_ROWS 8192
#define D_DIM  512
#define BM 128
#define BN 128
#define BK 32
#define NKS (D_DIM / BK)        // 16 k-steps per tile
#define NB  (N_ROWS / BM)       // 64 blocks
#define NTILES (NB * (NB + 1) / 2)   // 2080
#define LDS_STRIDE 40           // halves; 80B pitch, conflict-free
#define STAGES 3
#define STAGE_HALVES (2 * BM * LDS_STRIDE)       // 10240 halves = 20480 B
#define SMEM_BYTES (STAGES * STAGE_HALVES * 2)   // 61440 B

#define EXP10 22026.465794806718f
#define SCALE 14.426950408889634f   // (1/0.1)*log2(e), folded into g_fb

// ---- scratch ----
__device__ __nv_bfloat16 g_fa[N_ROWS * D_DIM];
__device__ __nv_bfloat16 g_fb[N_ROWS * D_DIM];
__device__ float g_pos[N_ROWS];
__device__ float g_tot[N_ROWS];
__device__ int   g_cl[N_ROWS];

// =============================== helpers ===================================
__device__ __forceinline__ uint32_t smem_u32(const void* p) {
    return (uint32_t)__cvta_generic_to_shared(p);
}
__device__ __forceinline__ void cp16(uint32_t saddr, const void* g) {
    asm volatile("cp.async.cg.shared.global [%0], [%1], 16;" :: "r"(saddr), "l"(g));
}
__device__ __forceinline__ void ldsm_x4(uint32_t addr, uint32_t& r0, uint32_t& r1,
                                        uint32_t& r2, uint32_t& r3) {
    asm volatile("ldmatrix.sync.aligned.m8n8.x4.shared.b16 {%0,%1,%2,%3},[%4];"
                 : "=r"(r0), "=r"(r1), "=r"(r2), "=r"(r3) : "r"(addr));
}
__device__ __forceinline__ void mma16816(float* c, uint32_t a0, uint32_t a1,
                                         uint32_t a2, uint32_t a3,
                                         uint32_t b0, uint32_t b1) {
    asm volatile(
        "mma.sync.aligned.m16n8k16.row.col.f32.bf16.bf16.f32 "
        "{%0,%1,%2,%3},{%4,%5,%6,%7},{%8,%9},{%0,%1,%2,%3};"
        : "+f"(c[0]), "+f"(c[1]), "+f"(c[2]), "+f"(c[3])
        : "r"(a0), "r"(a1), "r"(a2), "r"(a3), "r"(b0), "r"(b1));
}
__device__ __forceinline__ float ex2(float x) {
    float e;
    asm("ex2.approx.f32 %0, %1;" : "=f"(e) : "f"(x));
    return e;
}

// =============================== small kernels ==============================
__global__ void init_kernel(const int* ca, float* out) {
    int i = blockIdx.x * blockDim.x + threadIdx.x;
    if (i == 0) out[0] = 0.0f;
    if (i >= N_ROWS) return;
    bool is64 = (ca[1] == 0) && (ca[3] == 0) && (ca[5] == 0) && (ca[7] == 0);
    g_cl[i]  = is64 ? ca[2 * i] : ca[i];
    g_pos[i] = 0.0f;
    g_tot[i] = 0.0f;
}

__global__ void norm_kernel(const float* __restrict__ f) {
    int row = blockIdx.x;
    const float* fr = f + (size_t)row * D_DIM;
    float v[4];
    float ss = 0.0f;
#pragma unroll
    for (int k = 0; k < 4; k++) { v[k] = fr[threadIdx.x + 128 * k]; ss += v[k] * v[k]; }
#pragma unroll
    for (int o = 16; o; o >>= 1) ss += __shfl_xor_sync(0xFFFFFFFFu, ss, o);
    __shared__ float s[4];
    if ((threadIdx.x & 31) == 0) s[threadIdx.x >> 5] = ss;
    __syncthreads();
    ss = s[0] + s[1] + s[2] + s[3];
    float r = 1.0f / fmaxf(sqrtf(ss), 1e-12f);
#pragma unroll
    for (int k = 0; k < 4; k++) {
        float x = v[k] * r;
        size_t idx = (size_t)row * D_DIM + threadIdx.x + 128 * k;
        g_fa[idx] = __float2bfloat16(x);
        g_fb[idx] = __float2bfloat16(x * SCALE);
    }
}

__global__ void dummy_kernel() {}   // ncu capture alignment

__global__ void loss_kernel(float* __restrict__ out) {
    int i = blockIdx.x * blockDim.x + threadIdx.x;
    float sum = logf((g_tot[i] + 1e-8f) / g_pos[i]);
#pragma unroll
    for (int o = 16; o; o >>= 1) sum += __shfl_xor_sync(0xFFFFFFFFu, sum, o);
    __shared__ float s[8];
    if ((threadIdx.x & 31) == 0) s[threadIdx.x >> 5] = sum;
    __syncthreads();
    if (threadIdx.x < 32) {
        float v = (threadIdx.x < 8) ? s[threadIdx.x] : 0.0f;
#pragma unroll
        for (int o = 4; o; o >>= 1) v += __shfl_xor_sync(0xFFFFFFFFu, v, o);
        if (threadIdx.x == 0) atomicAdd(out, v);
    }
}

// =============================== main GEMM ==================================
// One 128x128 tile per CTA, upper triangle only (2080 CTAs).
// 128 threads = 4 warps in 2x2, warp tile 64x64.
__global__ void __launch_bounds__(128, 2) gemm_hmma() {
    extern __shared__ __nv_bfloat16 sm[];

    const int tid  = threadIdx.x;
    const int lane = tid & 31;
    const int w    = tid >> 5;
    const int wm   = w & 1;
    const int wn   = w >> 1;

    // ---- triangular tile map: t -> (bi, bj), bi <= bj ----
    const int t = blockIdx.x;
    int bi = (int)((129.0f - sqrtf(16641.0f - 8.0f * (float)t)) * 0.5f);
    while ((bi + 1) * NB - ((bi + 1) * bi) / 2 <= t) bi++;
    while (bi * NB - (bi * (bi - 1)) / 2 > t) bi--;
    const int bj = bi + (t - (bi * NB - (bi * (bi - 1)) / 2));
    const int i0 = bi * BM;
    const int j0 = bj * BN;
    const bool isdiag = (bi == bj);

    // ---- staging: thread -> row tid, 4 x 16B segments each for A and B ----
    const __nv_bfloat16* gA = g_fa + (size_t)(i0 + tid) * D_DIM;
    const __nv_bfloat16* gB = g_fb + (size_t)(j0 + tid) * D_DIM;
    const uint32_t sm_base = smem_u32(sm);
    const uint32_t sA_off = (uint32_t)(tid * LDS_STRIDE * 2);
    const uint32_t sB_off = sA_off + (uint32_t)(BM * LDS_STRIDE * 2);

    auto prefetch = [&](int g) {
        const int kk = g << 5;
        const uint32_t st = (uint32_t)(g % STAGES) * (STAGE_HALVES * 2);
#pragma unroll
        for (int seg = 0; seg < 4; seg++) {
            cp16(sm_base + st + sA_off + seg * 16, gA + kk + seg * 8);
            cp16(sm_base + st + sB_off + seg * 16, gB + kk + seg * 8);
        }
        asm volatile("cp.async.commit_group;" ::: "memory");
    };

    // ---- ldmatrix geometry ----
    const int a_row = wm * 64 + (lane & 15);
    const int a_col = (lane >> 4) << 3;
    const uint32_t a_off = (uint32_t)((a_row * LDS_STRIDE + a_col) * 2);
    const int b_row = wn * 64 + (lane & 7) + ((lane >> 4) << 3);
    const int b_col = ((lane >> 3) & 1) << 3;
    const uint32_t b_off = (uint32_t)((b_row * LDS_STRIDE + b_col) * 2) +
                           (uint32_t)(BM * LDS_STRIDE * 2);

    float acc[4][8][4];
#pragma unroll
    for (int mi = 0; mi < 4; mi++)
#pragma unroll
        for (int ni = 0; ni < 8; ni++)
#pragma unroll
            for (int v = 0; v < 4; v++) acc[mi][ni][v] = 0.0f;

    prefetch(0);
    prefetch(1);

    for (int g = 0; g < NKS; g++) {
        asm volatile("cp.async.wait_group 1;" ::: "memory");
        __syncthreads();
        if (g + 2 < NKS) prefetch(g + 2);

        const uint32_t stb = sm_base + (uint32_t)(g % STAGES) * (STAGE_HALVES * 2);
        const uint32_t sa = stb + a_off;
        const uint32_t sbb = stb + b_off;

#pragma unroll
        for (int s = 0; s < 2; s++) {
            uint32_t a[4][4];
#pragma unroll
            for (int mi = 0; mi < 4; mi++)
                ldsm_x4(sa + (uint32_t)((mi * 16 * LDS_STRIDE + s * 16) * 2),
                        a[mi][0], a[mi][1], a[mi][2], a[mi][3]);
#pragma unroll
            for (int np = 0; np < 4; np++) {
                uint32_t b0, b1, b2, b3;
                ldsm_x4(sbb + (uint32_t)((np * 16 * LDS_STRIDE + s * 16) * 2),
                        b0, b1, b2, b3);
#pragma unroll
                for (int mi = 0; mi < 4; mi++) {
                    mma16816(acc[mi][np * 2],     a[mi][0], a[mi][1], a[mi][2], a[mi][3], b0, b1);
                    mma16816(acc[mi][np * 2 + 1], a[mi][0], a[mi][1], a[mi][2], a[mi][3], b2, b3);
                }
            }
        }
    }

    // ---- epilogue: exp + masked row sums (block bi) and col sums (block bj) ----
    int ci_r[8], cj_c[16];
#pragma unroll
    for (int mi = 0; mi < 4; mi++)
#pragma unroll
        for (int h = 0; h < 2; h++)
            ci_r[mi * 2 + h] = g_cl[i0 + wm * 64 + mi * 16 + (lane >> 2) + h * 8];
#pragma unroll
    for (int ni = 0; ni < 8; ni++)
#pragma unroll
        for (int vb = 0; vb < 2; vb++)
            cj_c[ni * 2 + vb] = g_cl[j0 + wn * 64 + ni * 8 + (lane & 3) * 2 + vb];

    float tr[8], pr[8], tc[16], pc[16];
#pragma unroll
    for (int k = 0; k < 8; k++)  { tr[k] = 0.0f; pr[k] = 0.0f; }
#pragma unroll
    for (int k = 0; k < 16; k++) { tc[k] = 0.0f; pc[k] = 0.0f; }

#pragma unroll
    for (int mi = 0; mi < 4; mi++) {
#pragma unroll
        for (int ni = 0; ni < 8; ni++) {
#pragma unroll
            for (int v = 0; v < 4; v++) {
                const int h = v >> 1, vb = v & 1;
                float e = ex2(acc[mi][ni][v]);
                if (isdiag) {
                    const int rloc = wm * 64 + mi * 16 + (lane >> 2) + h * 8;
                    const int cloc = wn * 64 + ni * 8 + (lane & 3) * 2 + vb;
                    if (rloc == cloc) e = EXP10;
                }
                const int ridx = mi * 2 + h;
                const int cidx = ni * 2 + vb;
                const bool m = (ci_r[ridx] == cj_c[cidx]);
                tr[ridx] += e;
                if (m) pr[ridx] += e;
                if (!isdiag) {
                    tc[cidx] += e;
                    if (m) pc[cidx] += e;
                }
            }
        }
    }

    // rows: reduce over the 4 lanes sharing each row (lane&3)
#pragma unroll
    for (int k = 0; k < 8; k++) {
#pragma unroll
        for (int o = 1; o <= 2; o <<= 1) {
            tr[k] += __shfl_xor_sync(0xFFFFFFFFu, tr[k], o);
            pr[k] += __shfl_xor_sync(0xFFFFFFFFu, pr[k], o);
        }
    }
    if ((lane & 3) == 0) {
#pragma unroll
        for (int k = 0; k < 8; k++) {
            const int row = i0 + wm * 64 + (k >> 1) * 16 + (lane >> 2) + (k & 1) * 8;
            atomicAdd(&g_tot[row], tr[k]);
            atomicAdd(&g_pos[row], pr[k]);
        }
    }

    // cols: reduce over the 8 lane-groups (lane>>2) sharing each column
    if (!isdiag) {
#pragma unroll
        for (int k = 0; k < 16; k++) {
#pragma unroll
            for (int o = 4; o <= 16; o <<= 1) {
                tc[k] += __shfl_xor_sync(0xFFFFFFFFu, tc[k], o);
                pc[k] += __shfl_xor_sync(0xFFFFFFFFu, pc[k], o);
            }
        }
        if (lane < 4) {
#pragma unroll
            for (int k = 0; k < 16; k++) {
                const int col = j0 + wn * 64 + (k >> 1) * 8 + (lane & 3) * 2 + (k & 1);
                atomicAdd(&g_tot[col], tc[k]);
                atomicAdd(&g_pos[col], pc[k]);
            }
        }
    }
}

// =============================== launch =====================================
extern "C" void kernel_launch(void* const* d_in, const int* in_sizes, int n_in,
                              void* d_out, int out_size) {
    const float* feat = (const float*)d_in[0];
    const int*   ca   = (const int*)d_in[1];

    static bool attr_done = false;
    if (!attr_done) {
        cudaFuncSetAttribute(gemm_hmma, cudaFuncAttributeMaxDynamicSharedMemorySize,
                             SMEM_BYTES);
        attr_done = true;
    }

    init_kernel<<<(N_ROWS + 255) / 256, 256>>>(ca, (float*)d_out);
    norm_kernel<<<N_ROWS, 128>>>(feat);
    dummy_kernel<<<1, 32>>>();                   // shifts gemm to launch #4 for ncu -s 5
    gemm_hmma<<<NTILES, 128, SMEM_BYTES>>>();
    loss_kernel<<<N_ROWS / 256, 256>>>((float*)d_out);
}

// round 5
// speedup vs baseline: 2.5685x; 1.5187x over previous
#include <cuda_runtime.h>
#include <cuda_bf16.h>
#include <cstdint>

#define N_ROWS 8192
#define D_DIM  512
#define BM 128
#define BN 128
#define BK 32
#define NKS (D_DIM / BK)        // 16 k-steps per tile
#define NB  (N_ROWS / BM)       // 64 blocks
#define NTILES (NB * (NB + 1) / 2)   // 2080
#define LDS_STRIDE 40           // halves; 80B pitch, conflict-free
#define STAGES 3
#define STAGE_HALVES (2 * BM * LDS_STRIDE)       // 10240 halves
#define SMEM_BYTES (STAGES * STAGE_HALVES * 2)   // 61440 B

#define EXP10 22026.465794806718f
#define SCALE 14.426950408889634f   // (1/0.1)*log2(e), folded into g_fb

// ---- scratch ----
__device__ __nv_bfloat16 g_fa[N_ROWS * D_DIM];
__device__ __nv_bfloat16 g_fb[N_ROWS * D_DIM];
__device__ float g_pos[N_ROWS];
__device__ float g_tot[N_ROWS];
__device__ int   g_cl[N_ROWS];

// =============================== helpers ===================================
__device__ __forceinline__ uint32_t smem_u32(const void* p) {
    return (uint32_t)__cvta_generic_to_shared(p);
}
__device__ __forceinline__ void cp16(uint32_t saddr, const void* g) {
    asm volatile("cp.async.cg.shared.global [%0], [%1], 16;" :: "r"(saddr), "l"(g));
}
__device__ __forceinline__ void ldsm_x4(uint32_t addr, uint32_t& r0, uint32_t& r1,
                                        uint32_t& r2, uint32_t& r3) {
    asm volatile("ldmatrix.sync.aligned.m8n8.x4.shared.b16 {%0,%1,%2,%3},[%4];"
                 : "=r"(r0), "=r"(r1), "=r"(r2), "=r"(r3) : "r"(addr));
}
__device__ __forceinline__ void mma16816(float* c, uint32_t a0, uint32_t a1,
                                         uint32_t a2, uint32_t a3,
                                         uint32_t b0, uint32_t b1) {
    asm volatile(
        "mma.sync.aligned.m16n8k16.row.col.f32.bf16.bf16.f32 "
        "{%0,%1,%2,%3},{%4,%5,%6,%7},{%8,%9},{%0,%1,%2,%3};"
        : "+f"(c[0]), "+f"(c[1]), "+f"(c[2]), "+f"(c[3])
        : "r"(a0), "r"(a1), "r"(a2), "r"(a3), "r"(b0), "r"(b1));
}
__device__ __forceinline__ float ex2(float x) {
    float e;
    asm("ex2.approx.f32 %0, %1;" : "=f"(e) : "f"(x));
    return e;
}

// =============================== small kernels ==============================
__global__ void init_kernel(const int* ca, float* out) {
    int i = blockIdx.x * blockDim.x + threadIdx.x;
    if (i == 0) out[0] = 0.0f;
    if (i >= N_ROWS) return;
    bool is64 = (ca[1] == 0) && (ca[3] == 0) && (ca[5] == 0) && (ca[7] == 0);
    g_cl[i]  = is64 ? ca[2 * i] : ca[i];
    g_pos[i] = 0.0f;
    g_tot[i] = 0.0f;
}

__global__ void norm_kernel(const float* __restrict__ f) {
    int row = blockIdx.x;
    const float* fr = f + (size_t)row * D_DIM;
    float v[4];
    float ss = 0.0f;
#pragma unroll
    for (int k = 0; k < 4; k++) { v[k] = fr[threadIdx.x + 128 * k]; ss += v[k] * v[k]; }
#pragma unroll
    for (int o = 16; o; o >>= 1) ss += __shfl_xor_sync(0xFFFFFFFFu, ss, o);
    __shared__ float s[4];
    if ((threadIdx.x & 31) == 0) s[threadIdx.x >> 5] = ss;
    __syncthreads();
    ss = s[0] + s[1] + s[2] + s[3];
    float r = 1.0f / fmaxf(sqrtf(ss), 1e-12f);
#pragma unroll
    for (int k = 0; k < 4; k++) {
        float x = v[k] * r;
        size_t idx = (size_t)row * D_DIM + threadIdx.x + 128 * k;
        g_fa[idx] = __float2bfloat16(x);
        g_fb[idx] = __float2bfloat16(x * SCALE);
    }
}

__global__ void dummy_kernel() {}   // ncu capture alignment (-s 5 lands on gemm)

__global__ void loss_kernel(float* __restrict__ out) {
    int i = blockIdx.x * blockDim.x + threadIdx.x;
    float sum = logf((g_tot[i] + 1e-8f) / g_pos[i]);
#pragma unroll
    for (int o = 16; o; o >>= 1) sum += __shfl_xor_sync(0xFFFFFFFFu, sum, o);
    __shared__ float s[8];
    if ((threadIdx.x & 31) == 0) s[threadIdx.x >> 5] = sum;
    __syncthreads();
    if (threadIdx.x < 32) {
        float v = (threadIdx.x < 8) ? s[threadIdx.x] : 0.0f;
#pragma unroll
        for (int o = 4; o; o >>= 1) v += __shfl_xor_sync(0xFFFFFFFFu, v, o);
        if (threadIdx.x == 0) atomicAdd(out, v);
    }
}

// =============================== main GEMM ==================================
// One 128x128 upper-triangular tile per CTA (2080 CTAs).
// 256 threads = 8 warps (4 M x 2 N), warp tile 32x64.
__global__ void __launch_bounds__(256, 2) gemm_hmma() {
    extern __shared__ __nv_bfloat16 sm[];

    const int tid  = threadIdx.x;
    const int lane = tid & 31;
    const int w    = tid >> 5;
    const int wm   = w & 3;       // 4 M-warps
    const int wn   = w >> 2;      // 2 N-warps

    // ---- triangular tile map: t -> (bi, bj), bi <= bj ----
    const int t = blockIdx.x;
    int bi = (int)((129.0f - sqrtf(16641.0f - 8.0f * (float)t)) * 0.5f);
    while ((bi + 1) * NB - ((bi + 1) * bi) / 2 <= t) bi++;
    while (bi * NB - (bi * (bi - 1)) / 2 > t) bi--;
    const int bj = bi + (t - (bi * NB - (bi * (bi - 1)) / 2));
    const int i0 = bi * BM;
    const int j0 = bj * BN;
    const bool isdiag = (bi == bj);

    // ---- cp.async staging: 256 threads, rows grow0 & grow0+64, 16B segs ----
    const int grow0 = tid >> 2;
    const int gcol  = (tid & 3) * 8;
    const uint32_t sm_base = smem_u32(sm);
    const uint32_t s_off0 = (uint32_t)((grow0 * LDS_STRIDE + gcol) * 2);
    const uint32_t s_off1 = (uint32_t)(((grow0 + 64) * LDS_STRIDE + gcol) * 2);
    const __nv_bfloat16* gA0 = g_fa + (size_t)(i0 + grow0) * D_DIM + gcol;
    const __nv_bfloat16* gB0 = g_fb + (size_t)(j0 + grow0) * D_DIM + gcol;

    auto prefetch = [&](int g) {
        const int kk = g << 5;
        const uint32_t st = (uint32_t)(g % STAGES) * (STAGE_HALVES * 2);
        cp16(sm_base + st + s_off0, gA0 + kk);
        cp16(sm_base + st + s_off1, gA0 + kk + 64 * D_DIM);
        const uint32_t bs = st + (uint32_t)(BM * LDS_STRIDE * 2);
        cp16(sm_base + bs + s_off0, gB0 + kk);
        cp16(sm_base + bs + s_off1, gB0 + kk + 64 * D_DIM);
        asm volatile("cp.async.commit_group;" ::: "memory");
    };

    // ---- ldmatrix geometry ----
    const int a_row = wm * 32 + (lane & 15);
    const int a_col = (lane >> 4) << 3;
    const uint32_t a_off = (uint32_t)((a_row * LDS_STRIDE + a_col) * 2);
    const int b_row = wn * 64 + (lane & 7) + ((lane >> 4) << 3);
    const int b_col = ((lane >> 3) & 1) << 3;
    const uint32_t b_off = (uint32_t)((b_row * LDS_STRIDE + b_col) * 2) +
                           (uint32_t)(BM * LDS_STRIDE * 2);

    float acc[2][8][4];
#pragma unroll
    for (int mi = 0; mi < 2; mi++)
#pragma unroll
        for (int ni = 0; ni < 8; ni++)
#pragma unroll
            for (int v = 0; v < 4; v++) acc[mi][ni][v] = 0.0f;

    prefetch(0);
    prefetch(1);

    for (int g = 0; g < NKS; g++) {
        asm volatile("cp.async.wait_group 1;" ::: "memory");
        __syncthreads();
        if (g + 2 < NKS) prefetch(g + 2);

        const uint32_t stb = sm_base + (uint32_t)(g % STAGES) * (STAGE_HALVES * 2);
        const uint32_t sa = stb + a_off;
        const uint32_t sbb = stb + b_off;

#pragma unroll
        for (int s = 0; s < 2; s++) {
            uint32_t a[2][4];
#pragma unroll
            for (int mi = 0; mi < 2; mi++)
                ldsm_x4(sa + (uint32_t)((mi * 16 * LDS_STRIDE + s * 16) * 2),
                        a[mi][0], a[mi][1], a[mi][2], a[mi][3]);
#pragma unroll
            for (int np = 0; np < 4; np++) {
                uint32_t b0, b1, b2, b3;
                ldsm_x4(sbb + (uint32_t)((np * 16 * LDS_STRIDE + s * 16) * 2),
                        b0, b1, b2, b3);
#pragma unroll
                for (int mi = 0; mi < 2; mi++) {
                    mma16816(acc[mi][np * 2],     a[mi][0], a[mi][1], a[mi][2], a[mi][3], b0, b1);
                    mma16816(acc[mi][np * 2 + 1], a[mi][0], a[mi][1], a[mi][2], a[mi][3], b2, b3);
                }
            }
        }
    }

    // ---- epilogue: rows -> block bi, cols -> block bj (symmetric reuse) ----
    const int rbase = wm * 32 + (lane >> 2);
    int ci[4];
#pragma unroll
    for (int r = 0; r < 4; r++)
        ci[r] = g_cl[i0 + rbase + (r >> 1) * 16 + (r & 1) * 8];

    float tr[4] = {0, 0, 0, 0}, pr[4] = {0, 0, 0, 0};

#pragma unroll
    for (int ni = 0; ni < 8; ni++) {
        const int colb = wn * 64 + ni * 8 + (lane & 3) * 2;
        const int2 cjp = *(const int2*)&g_cl[j0 + colb];
        float ct[2] = {0, 0}, cp[2] = {0, 0};
#pragma unroll
        for (int mi = 0; mi < 2; mi++) {
#pragma unroll
            for (int v = 0; v < 4; v++) {
                const int h = v >> 1, vb = v & 1;
                const int ridx = mi * 2 + h;
                float e = ex2(acc[mi][ni][v]);
                if (isdiag && (rbase + mi * 16 + h * 8 == colb + vb)) e = EXP10;
                const bool m = (ci[ridx] == (vb ? cjp.y : cjp.x));
                tr[ridx] += e;
                if (m) pr[ridx] += e;
                ct[vb] += e;
                if (m) cp[vb] += e;
            }
        }
        if (!isdiag) {
#pragma unroll
            for (int o = 4; o <= 16; o <<= 1) {
#pragma unroll
                for (int vb = 0; vb < 2; vb++) {
                    ct[vb] += __shfl_xor_sync(0xFFFFFFFFu, ct[vb], o);
                    cp[vb] += __shfl_xor_sync(0xFFFFFFFFu, cp[vb], o);
                }
            }
            if (lane < 4) {
                atomicAdd(&g_tot[j0 + colb + 0], ct[0]);
                atomicAdd(&g_tot[j0 + colb + 1], ct[1]);
                atomicAdd(&g_pos[j0 + colb + 0], cp[0]);
                atomicAdd(&g_pos[j0 + colb + 1], cp[1]);
            }
        }
    }

    // rows: reduce over the 4 lanes (lane&3) sharing each row
#pragma unroll
    for (int r = 0; r < 4; r++) {
#pragma unroll
        for (int o = 1; o <= 2; o <<= 1) {
            tr[r] += __shfl_xor_sync(0xFFFFFFFFu, tr[r], o);
            pr[r] += __shfl_xor_sync(0xFFFFFFFFu, pr[r], o);
        }
    }
    if ((lane & 3) == 0) {
#pragma unroll
        for (int r = 0; r < 4; r++) {
            const int row = i0 + rbase + (r >> 1) * 16 + (r & 1) * 8;
            atomicAdd(&g_tot[row], tr[r]);
            atomicAdd(&g_pos[row], pr[r]);
        }
    }
}

// =============================== launch =====================================
extern "C" void kernel_launch(void* const* d_in, const int* in_sizes, int n_in,
                              void* d_out, int out_size) {
    const float* feat = (const float*)d_in[0];
    const int*   ca   = (const int*)d_in[1];

    static bool attr_done = false;
    if (!attr_done) {
        cudaFuncSetAttribute(gemm_hmma, cudaFuncAttributeMaxDynamicSharedMemorySize,
                             SMEM_BYTES);
        attr_done = true;
    }

    init_kernel<<<(N_ROWS + 255) / 256, 256>>>(ca, (float*)d_out);
    norm_kernel<<<N_ROWS, 128>>>(feat);
    dummy_kernel<<<1, 32>>>();
    gemm_hmma<<<NTILES, 256, SMEM_BYTES>>>();
    loss_kernel<<<N_ROWS / 256, 256>>>((float*)d_out);
}